// round 1
// baseline (speedup 1.0000x reference)
#include <cuda_runtime.h>
#include <cuda_bf16.h>
#include <cstdint>

#define NIMG 8
#define NA   3
#define HH   100
#define WW   100
#define NANC 30000          // H*W*A
#define PRE  2000
#define PREP 2048           // padded to pow2 for bitonic sort
#define POST 1000
#define NWRD 32             // ceil(2000/64) mask words per row
#define IMGW 1600.0f
#define BBOX_CLIP 4.135166556742356f   // log(1000/16)
#define NMS_THR 0.7f

// ---------------- device-global scratch (no runtime allocation) ----------------
__device__ float4             g_boxes[NIMG][PRE];
__device__ float              g_scores[NIMG][PRE];
__device__ unsigned char      g_valid[NIMG][PRE];
__device__ unsigned long long g_mask[NIMG][PRE][NWRD];   // ~4.1 MB

// =============================================================================
// Kernel A: scores -> radix-select threshold -> compact -> bitonic sort ->
//           decode/clip/valid for top-2000.  One block per image.
// =============================================================================
__global__ __launch_bounds__(1024)
void topk_decode_kernel(const float* __restrict__ obj_all,
                        const float* __restrict__ reg_all,
                        const float* __restrict__ anc_all)
{
    extern __shared__ unsigned char smem_raw[];
    unsigned int*       s_sb   = (unsigned int*)smem_raw;                // 30000 u32 (120000 B)
    unsigned long long* s_keys = (unsigned long long*)(smem_raw + 120000); // 2048 u64 (16384 B)

    __shared__ unsigned int s_hist[256];
    __shared__ unsigned int s_cnt;
    __shared__ unsigned int s_prefix;
    __shared__ int          s_K;

    const int img = blockIdx.x;
    const int tid = threadIdx.x;
    const float* obj = obj_all + (size_t)img * NA * HH * WW;

    // ---- phase 1: sigmoid scores as monotonic positive-float bits ----
    for (int i = tid; i < NANC; i += 1024) {
        int hw = i / NA;
        int a  = i - hw * NA;
        float o = obj[a * (HH * WW) + hw];
        float s = 1.0f / (1.0f + expf(-o));
        s_sb[i] = __float_as_uint(s);          // scores in (0,1): bits monotonic
    }
    if (tid == 0) { s_prefix = 0; s_K = PRE; }
    __syncthreads();

    // ---- phase 2: 4-pass MSB radix select for the PRE-th largest value ----
    unsigned int pmask = 0;
    for (int pass = 0; pass < 4; ++pass) {
        int shift = 24 - 8 * pass;
        if (tid < 256) s_hist[tid] = 0;
        __syncthreads();
        unsigned int prefix = s_prefix;
        for (int i = tid; i < NANC; i += 1024) {
            unsigned int v = s_sb[i];
            if ((v & pmask) == prefix)
                atomicAdd(&s_hist[(v >> shift) & 255u], 1u);
        }
        __syncthreads();
        if (tid == 0) {
            int K = s_K;
            unsigned int c = 0;
            int b = 255;
            for (; b >= 0; --b) {
                c += s_hist[b];
                if ((int)c >= K) break;
            }
            s_K = s_K - (int)(c - s_hist[b]);          // still needed within bin b
            s_prefix = s_prefix | ((unsigned int)b << shift);
        }
        pmask |= (0xFFu << shift);
        __syncthreads();
    }
    const unsigned int T = s_prefix;   // exact bits of the PRE-th largest score

    // ---- phase 3: compact candidates >= T ----
    if (tid == 0) s_cnt = 0;
    __syncthreads();
    for (int i = tid; i < NANC; i += 1024) {
        unsigned int v = s_sb[i];
        if (v >= T) {
            unsigned int pos = atomicAdd(&s_cnt, 1u);
            if (pos < PREP)
                s_keys[pos] = ((unsigned long long)v << 32) |
                              (unsigned long long)(~(unsigned int)i);
        }
    }
    __syncthreads();
    unsigned int n = s_cnt; if (n > PREP) n = PREP;
    for (int i = tid; i < PREP; i += 1024)
        if (i >= (int)n) s_keys[i] = 0ULL;
    __syncthreads();

    // ---- phase 4: bitonic sort (descending) of 2048 keys ----
    for (int k = 2; k <= PREP; k <<= 1) {
        for (int j = k >> 1; j > 0; j >>= 1) {
            for (int i = tid; i < PREP; i += 1024) {
                int l = i ^ j;
                if (l > i) {
                    unsigned long long a = s_keys[i];
                    unsigned long long b = s_keys[l];
                    bool up = ((i & k) == 0);
                    if ((a < b) == up) { s_keys[i] = b; s_keys[l] = a; }
                }
            }
            __syncthreads();
        }
    }

    // ---- phase 5: decode / clip / validity for top PRE ----
    const float* reg = reg_all + (size_t)img * NA * 4 * HH * WW;
    const float4* anc = (const float4*)anc_all + (size_t)img * NANC;
    for (int j = tid; j < PRE; j += 1024) {
        unsigned long long key = s_keys[j];
        unsigned int idx = ~(unsigned int)(key & 0xFFFFFFFFull);
        float score = __uint_as_float((unsigned int)(key >> 32));

        int hw = idx / NA;
        int a  = idx - hw * NA;
        const float* rb = reg + (a * 4) * (HH * WW) + hw;
        float dx = rb[0];
        float dy = rb[HH * WW];
        float dw = rb[2 * HH * WW];
        float dh = rb[3 * HH * WW];
        dw = fminf(dw, BBOX_CLIP);
        dh = fminf(dh, BBOX_CLIP);

        float4 A4 = anc[idx];
        float w  = A4.z - A4.x + 1.0f;
        float h  = A4.w - A4.y + 1.0f;
        float cx = A4.x + 0.5f * w;
        float cy = A4.y + 0.5f * h;

        float pcx = dx * w + cx;
        float pcy = dy * h + cy;
        float pw  = expf(dw) * w;
        float ph  = expf(dh) * h;

        float x1 = pcx - 0.5f * pw;
        float y1 = pcy - 0.5f * ph;
        float x2 = pcx + 0.5f * pw - 1.0f;
        float y2 = pcy + 0.5f * ph - 1.0f;

        x1 = fminf(fmaxf(x1, 0.0f), IMGW - 1.0f);
        x2 = fminf(fmaxf(x2, 0.0f), IMGW - 1.0f);
        y1 = fminf(fmaxf(y1, 0.0f), IMGW - 1.0f);
        y2 = fminf(fmaxf(y2, 0.0f), IMGW - 1.0f);

        float ws = x2 - x1 + 1.0f;
        float hs = y2 - y1 + 1.0f;
        float xc = x1 + ws * 0.5f;
        float yc = y1 + hs * 0.5f;
        unsigned char v = (ws >= 0.0f) & (hs >= 0.0f) & (xc < IMGW) & (yc < IMGW);

        g_boxes[img][j]  = make_float4(x1, y1, x2, y2);
        g_scores[img][j] = score;
        g_valid[img][j]  = v;
    }
}

// =============================================================================
// Kernel B: NMS suppression bitmask.  grid (colBlk=32, rowBlk=32, img=8), 64 thr
// =============================================================================
__global__ __launch_bounds__(64)
void nms_mask_kernel()
{
    const int img    = blockIdx.z;
    const int rowBlk = blockIdx.y;
    const int colBlk = blockIdx.x;
    const int tid    = threadIdx.x;
    const int row    = rowBlk * 64 + tid;

    if (colBlk < rowBlk) {                 // strictly lower-triangular: all zero
        if (row < PRE) g_mask[img][row][colBlk] = 0ULL;
        return;
    }

    __shared__ float4 s_col[64];
    const int colBase = colBlk * 64;
    const int c = colBase + tid;
    if (c < PRE) s_col[tid] = g_boxes[img][c];
    __syncthreads();

    if (row >= PRE) return;

    float4 rb = g_boxes[img][row];
    float rArea = (rb.z - rb.x + 1.0f) * (rb.w - rb.y + 1.0f);
    unsigned long long bits = 0ULL;
    int nCols = PRE - colBase; if (nCols > 64) nCols = 64;

    for (int jj = 0; jj < nCols; ++jj) {
        int col = colBase + jj;
        if (col <= row) continue;
        float4 cb = s_col[jj];
        float xx1 = fmaxf(rb.x, cb.x);
        float yy1 = fmaxf(rb.y, cb.y);
        float xx2 = fminf(rb.z, cb.z);
        float yy2 = fminf(rb.w, cb.w);
        float iw = fmaxf(xx2 - xx1 + 1.0f, 0.0f);
        float ih = fmaxf(yy2 - yy1 + 1.0f, 0.0f);
        float inter = iw * ih;
        float cArea = (cb.z - cb.x + 1.0f) * (cb.w - cb.y + 1.0f);
        float iou = inter / (rArea + cArea - inter);
        if (iou > NMS_THR) bits |= (1ULL << jj);
    }
    g_mask[img][row][colBlk] = bits;
}

// =============================================================================
// Kernel C: sequential greedy scan (1 warp/image) + select + write outputs.
// Output layout: boxes[8*1000*4] | scores[8*1000] | valid[8*1000]  (float32)
// =============================================================================
__global__ __launch_bounds__(256)
void nms_reduce_kernel(float* __restrict__ out)
{
    const int img = blockIdx.x;
    const int tid = threadIdx.x;

    float* outB = out;                       // (8,1000,4)
    float* outS = out + NIMG * POST * 4;     // (8,1000)
    float* outV = out + NIMG * POST * 5;     // (8,1000)

    for (int i = tid; i < POST * 4; i += 256) outB[img * POST * 4 + i] = 0.0f;
    for (int i = tid; i < POST;     i += 256) {
        outS[img * POST + i] = 0.0f;
        outV[img * POST + i] = 0.0f;
    }
    __syncthreads();

    if (tid < 32) {
        const int lane = tid;
        unsigned long long rw = 0ULL;                    // lane owns removed word `lane`
        unsigned long long m  = g_mask[img][0][lane];    // prefetched mask row
        unsigned char v = g_valid[img][0];
        int k = 0;
        for (int i = 0; i < PRE; ++i) {
            unsigned long long mn = (i + 1 < PRE) ? g_mask[img][i + 1][lane] : 0ULL;
            unsigned char vn = (i + 1 < PRE) ? g_valid[img][i + 1] : 0;
            unsigned long long wrd = __shfl_sync(0xFFFFFFFFu, rw, i >> 6);
            bool removed = (wrd >> (i & 63)) & 1ULL;
            if (!removed && v) {
                if (lane == 0) {
                    float4 b = g_boxes[img][i];
                    ((float4*)outB)[img * POST + k] = b;
                    outS[img * POST + k] = g_scores[img][i];
                    outV[img * POST + k] = 1.0f;
                }
                rw |= m;
                ++k;
                if (k >= POST) break;
            }
            m = mn;
            v = vn;
        }
    }
}

// =============================================================================
extern "C" void kernel_launch(void* const* d_in, const int* in_sizes, int n_in,
                              void* d_out, int out_size)
{
    const float* obj = (const float*)d_in[0];   // (8,3,100,100)
    const float* reg = (const float*)d_in[1];   // (8,12,100,100)
    const float* anc = (const float*)d_in[2];   // (8,30000,4)
    float* out = (float*)d_out;

    const int smemA = 120000 + PREP * 8;        // 136384 bytes
    static bool attr_done = false;
    // setting an attribute is idempotent & deterministic; do it every call
    cudaFuncSetAttribute(topk_decode_kernel,
                         cudaFuncAttributeMaxDynamicSharedMemorySize, smemA);
    (void)attr_done; (void)in_sizes; (void)n_in; (void)out_size;

    topk_decode_kernel<<<NIMG, 1024, smemA>>>(obj, reg, anc);
    dim3 gB(NWRD, NWRD, NIMG);
    nms_mask_kernel<<<gB, 64>>>();
    nms_reduce_kernel<<<NIMG, 256>>>(out);
}

// round 3
// speedup vs baseline: 1.8299x; 1.8299x over previous
#include <cuda_runtime.h>
#include <cuda_bf16.h>
#include <cstdint>

#define NIMG 8
#define NA   3
#define HH   100
#define WW   100
#define NHW  10000
#define NANC 30000          // H*W*A
#define PRE  2000
#define PREP 2048           // padded to pow2 for bitonic sort
#define POST 1000
#define NWRD 32             // ceil(2000/64) mask words per row
#define IMGW 1600.0f
#define BBOX_CLIP 4.135166556742356f   // log(1000/16)
#define NMS_THR 0.7f
#define PFD  16             // prefetch depth in kernel C (2000 % 16 == 0)

// ---------------- device-global scratch (no runtime allocation) ----------------
__device__ unsigned int      g_sb[NIMG][NANC];            // sigmoid score bits, anchor order
__device__ float4             g_boxes[NIMG][PRE];
__device__ float              g_scores[NIMG][PRE];
__device__ unsigned char      g_valid[NIMG][PRE];
__device__ unsigned long long g_mask[NIMG][PRE][NWRD];    // ~4.1 MB

// =============================================================================
// Kernel 0: full-chip sigmoid + layout transform (N,A,H,W) -> [img][hw*3+a]
// =============================================================================
__global__ __launch_bounds__(256)
void sigmoid_kernel(const float* __restrict__ obj_all)
{
    int gid = blockIdx.x * 256 + threadIdx.x;
    if (gid >= NIMG * NANC) return;
    int img = gid / NANC;
    int r   = gid - img * NANC;      // r = a*NHW + hw  (input memory order -> coalesced read)
    int a   = r / NHW;
    int hw  = r - a * NHW;
    float o = obj_all[gid];
    float s = 1.0f / (1.0f + expf(-o));
    g_sb[img][hw * NA + a] = __float_as_uint(s);   // scores in (0,1): bits monotonic
}

// =============================================================================
// Kernel A: radix-select threshold -> compact -> bitonic sort -> decode/clip.
// One block (1024 thr) per image.
// =============================================================================
__global__ __launch_bounds__(1024)
void topk_decode_kernel(const float* __restrict__ reg_all,
                        const float* __restrict__ anc_all)
{
    extern __shared__ unsigned char smem_raw[];
    unsigned int*       s_sb   = (unsigned int*)smem_raw;                  // 30000 u32
    unsigned long long* s_keys = (unsigned long long*)(smem_raw + 120000); // 2048 u64

    __shared__ unsigned int s_hist[256];
    __shared__ unsigned int s_scan[256];
    __shared__ unsigned int s_cnt;
    __shared__ unsigned int s_prefix;
    __shared__ int          s_K;

    const int img = blockIdx.x;
    const int tid = threadIdx.x;

    // ---- phase 1: coalesced vector copy of score bits into smem ----
    {
        const uint4* src = (const uint4*)g_sb[img];          // 30000/4 = 7500 uint4
        uint4* dst = (uint4*)s_sb;
        for (int i = tid; i < NANC / 4; i += 1024) dst[i] = src[i];
    }
    if (tid == 0) { s_prefix = 0; s_K = PRE; }
    __syncthreads();

    // ---- phase 2: 4-pass MSB radix select for the PRE-th largest value ----
    unsigned int pmask = 0;
    for (int pass = 0; pass < 4; ++pass) {
        int shift = 24 - 8 * pass;
        if (tid < 256) s_hist[tid] = 0;
        __syncthreads();
        unsigned int prefix = s_prefix;
        for (int i = tid; i < NANC; i += 1024) {
            unsigned int v = s_sb[i];
            if ((v & pmask) == prefix)
                atomicAdd(&s_hist[(v >> shift) & 255u], 1u);
        }
        __syncthreads();
        // parallel inclusive suffix-sum over 256 bins
        if (tid < 256) s_scan[tid] = s_hist[tid];
        __syncthreads();
        for (int off = 1; off < 256; off <<= 1) {
            unsigned int add = 0;
            if (tid < 256) add = (tid + off < 256) ? s_scan[tid + off] : 0u;
            __syncthreads();
            if (tid < 256) s_scan[tid] += add;
            __syncthreads();
        }
        int Kc = s_K;
        __syncthreads();
        if (tid < 256) {
            unsigned int cs  = s_scan[tid];
            unsigned int nxt = (tid < 255) ? s_scan[tid + 1] : 0u;
            if ((int)cs >= Kc && (int)nxt < Kc) {
                s_K = Kc - (int)nxt;                       // remaining within this bin
                s_prefix = s_prefix | ((unsigned int)tid << shift);
            }
        }
        pmask |= (0xFFu << shift);
        __syncthreads();
    }
    const unsigned int T = s_prefix;   // exact bits of the PRE-th largest score

    // ---- phase 3: compact candidates >= T ----
    if (tid == 0) s_cnt = 0;
    __syncthreads();
    for (int i = tid; i < NANC; i += 1024) {
        unsigned int v = s_sb[i];
        if (v >= T) {
            unsigned int pos = atomicAdd(&s_cnt, 1u);
            if (pos < PREP)
                s_keys[pos] = ((unsigned long long)v << 32) |
                              (unsigned long long)(~(unsigned int)i);
        }
    }
    __syncthreads();
    unsigned int n = s_cnt; if (n > PREP) n = PREP;
    for (int i = tid; i < PREP; i += 1024)
        if (i >= (int)n) s_keys[i] = 0ULL;
    __syncthreads();

    // ---- phase 4: bitonic sort (descending) of 2048 keys ----
    for (int k = 2; k <= PREP; k <<= 1) {
        for (int j = k >> 1; j > 0; j >>= 1) {
            for (int i = tid; i < PREP; i += 1024) {
                int l = i ^ j;
                if (l > i) {
                    unsigned long long a = s_keys[i];
                    unsigned long long b = s_keys[l];
                    bool up = ((i & k) == 0);
                    if ((a < b) == up) { s_keys[i] = b; s_keys[l] = a; }
                }
            }
            __syncthreads();
        }
    }

    // ---- phase 5: decode / clip / validity for top PRE ----
    const float* reg = reg_all + (size_t)img * NA * 4 * NHW;
    const float4* anc = (const float4*)anc_all + (size_t)img * NANC;
    for (int j = tid; j < PRE; j += 1024) {
        unsigned long long key = s_keys[j];
        unsigned int idx = ~(unsigned int)(key & 0xFFFFFFFFull);
        float score = __uint_as_float((unsigned int)(key >> 32));

        int hw = idx / NA;
        int a  = idx - hw * NA;
        const float* rb = reg + (a * 4) * NHW + hw;
        float dx = rb[0];
        float dy = rb[NHW];
        float dw = rb[2 * NHW];
        float dh = rb[3 * NHW];
        dw = fminf(dw, BBOX_CLIP);
        dh = fminf(dh, BBOX_CLIP);

        float4 A4 = anc[idx];
        float w  = A4.z - A4.x + 1.0f;
        float h  = A4.w - A4.y + 1.0f;
        float cx = A4.x + 0.5f * w;
        float cy = A4.y + 0.5f * h;

        float pcx = dx * w + cx;
        float pcy = dy * h + cy;
        float pw  = expf(dw) * w;
        float ph  = expf(dh) * h;

        float x1 = pcx - 0.5f * pw;
        float y1 = pcy - 0.5f * ph;
        float x2 = pcx + 0.5f * pw - 1.0f;
        float y2 = pcy + 0.5f * ph - 1.0f;

        x1 = fminf(fmaxf(x1, 0.0f), IMGW - 1.0f);
        x2 = fminf(fmaxf(x2, 0.0f), IMGW - 1.0f);
        y1 = fminf(fmaxf(y1, 0.0f), IMGW - 1.0f);
        y2 = fminf(fmaxf(y2, 0.0f), IMGW - 1.0f);

        float ws = x2 - x1 + 1.0f;
        float hs = y2 - y1 + 1.0f;
        float xc = x1 + ws * 0.5f;
        float yc = y1 + hs * 0.5f;
        unsigned char v = (ws >= 0.0f) & (hs >= 0.0f) & (xc < IMGW) & (yc < IMGW);

        g_boxes[img][j]  = make_float4(x1, y1, x2, y2);
        g_scores[img][j] = score;
        g_valid[img][j]  = v;
    }
}

// =============================================================================
// Kernel B: NMS suppression bitmask. grid (colBlk=32, rowQuad=8, img=8), 256 thr
// =============================================================================
__global__ __launch_bounds__(256)
void nms_mask_kernel()
{
    const int img    = blockIdx.z;
    const int colBlk = blockIdx.x;
    const int row    = blockIdx.y * 256 + threadIdx.x;

    __shared__ float4 s_col[64];
    const int colBase = colBlk * 64;
    if (threadIdx.x < 64) {
        int c = colBase + threadIdx.x;
        if (c < PRE) s_col[threadIdx.x] = g_boxes[img][c];
    }
    __syncthreads();

    if (row >= PRE) return;
    if (colBlk < (row >> 6)) {             // tile entirely below diagonal
        g_mask[img][row][colBlk] = 0ULL;
        return;
    }

    float4 rb = g_boxes[img][row];
    float rArea = (rb.z - rb.x + 1.0f) * (rb.w - rb.y + 1.0f);
    unsigned long long bits = 0ULL;
    int nCols = PRE - colBase; if (nCols > 64) nCols = 64;

    for (int jj = 0; jj < nCols; ++jj) {
        int col = colBase + jj;
        if (col <= row) continue;
        float4 cb = s_col[jj];
        float xx1 = fmaxf(rb.x, cb.x);
        float yy1 = fmaxf(rb.y, cb.y);
        float xx2 = fminf(rb.z, cb.z);
        float yy2 = fminf(rb.w, cb.w);
        float iw = fmaxf(xx2 - xx1 + 1.0f, 0.0f);
        float ih = fmaxf(yy2 - yy1 + 1.0f, 0.0f);
        float inter = iw * ih;
        float cArea = (cb.z - cb.x + 1.0f) * (cb.w - cb.y + 1.0f);
        float iou = inter / (rArea + cArea - inter);
        if (iou > NMS_THR) bits |= (1ULL << jj);
    }
    g_mask[img][row][colBlk] = bits;
}

// =============================================================================
// Kernel C: greedy scan, 1 warp/image, register prefetch depth PFD.
// Output layout: boxes[8*1000*4] | scores[8*1000] | valid[8*1000]  (float32)
// =============================================================================
__global__ __launch_bounds__(256)
void nms_reduce_kernel(float* __restrict__ out)
{
    const int img = blockIdx.x;
    const int tid = threadIdx.x;

    __shared__ unsigned long long s_validw[NWRD];
    __shared__ int s_kept[POST];
    __shared__ int s_nk;

    float* outB = out;                       // (8,1000,4)
    float* outS = out + NIMG * POST * 4;     // (8,1000)
    float* outV = out + NIMG * POST * 5;     // (8,1000)

    if (tid >= 32) {
        // warps 1..7: zero the output region for this image (overlaps with scan)
        int t = tid - 32;
        for (int i = t; i < POST * 4; i += 224) outB[img * POST * 4 + i] = 0.0f;
        for (int i = t; i < POST;     i += 224) {
            outS[img * POST + i] = 0.0f;
            outV[img * POST + i] = 0.0f;
        }
    } else {
        const int lane = tid;
        // pack valid bytes into 64-bit words (lane owns word `lane`)
        {
            const unsigned long long* vp = (const unsigned long long*)g_valid[img];
            unsigned long long bits = 0ULL;
            #pragma unroll
            for (int q = 0; q < 8; ++q) {
                unsigned long long v8 = vp[lane * 8 + q];
                #pragma unroll
                for (int b = 0; b < 8; ++b)
                    if ((v8 >> (8 * b)) & 0xFFull) bits |= 1ULL << (q * 8 + b);
            }
            s_validw[lane] = bits;
        }
        __syncwarp();

        unsigned long long rw = 0ULL;            // lane owns removed word `lane`
        unsigned long long buf[PFD];
        #pragma unroll
        for (int d = 0; d < PFD; ++d) buf[d] = g_mask[img][d][lane];

        int k = 0;
        unsigned long long cur = 0ULL, vw = 0ULL;
        for (int base = 0; base < PRE; base += PFD) {
            #pragma unroll
            for (int d = 0; d < PFD; ++d) {
                int i = base + d;
                unsigned long long m = buf[d];
                int pf = i + PFD;
                buf[d] = (pf < PRE) ? g_mask[img][pf][lane] : 0ULL;  // deep prefetch
                int w = i >> 6;
                if ((i & 63) == 0) {
                    cur = __shfl_sync(0xFFFFFFFFu, rw, w);   // uniform branch
                    vw  = s_validw[w];
                }
                unsigned long long bit = 1ULL << (i & 63);
                if (!(cur & bit) && (vw & bit)) {            // uniform condition
                    rw |= m;
                    cur |= __shfl_sync(0xFFFFFFFFu, m, w);
                    if (lane == 0) s_kept[k] = i;
                    if (++k >= POST) goto scan_done;
                }
            }
        }
    scan_done:
        if (lane == 0) s_nk = k;
    }
    __syncthreads();

    const int nk = s_nk;
    for (int j = tid; j < nk; j += 256) {
        int i = s_kept[j];
        float4 b = g_boxes[img][i];
        ((float4*)outB)[img * POST + j] = b;
        outS[img * POST + j] = g_scores[img][i];
        outV[img * POST + j] = 1.0f;
    }
}

// =============================================================================
extern "C" void kernel_launch(void* const* d_in, const int* in_sizes, int n_in,
                              void* d_out, int out_size)
{
    const float* obj = (const float*)d_in[0];   // (8,3,100,100)
    const float* reg = (const float*)d_in[1];   // (8,12,100,100)
    const float* anc = (const float*)d_in[2];   // (8,30000,4)
    float* out = (float*)d_out;
    (void)in_sizes; (void)n_in; (void)out_size;

    const int smemA = 120000 + PREP * 8;        // 136384 bytes dynamic
    cudaFuncSetAttribute(topk_decode_kernel,
                         cudaFuncAttributeMaxDynamicSharedMemorySize, smemA);

    sigmoid_kernel<<<(NIMG * NANC + 255) / 256, 256>>>(obj);
    topk_decode_kernel<<<NIMG, 1024, smemA>>>(reg, anc);
    dim3 gB(NWRD, 8, NIMG);
    nms_mask_kernel<<<gB, 256>>>();
    nms_reduce_kernel<<<NIMG, 256>>>(out);
}